// round 2
// baseline (speedup 1.0000x reference)
#include <cuda_runtime.h>
#include <cuda_bf16.h>

#define SS 512
#define BB 256
#define II 64
#define HH 512
#define G4 2048
#define NCTA 128

// ---------------- static device scratch (no allocs allowed) ----------------
__device__ float          g_xw[(size_t)SS * BB * G4];      // 1 GB: per-layer input projection
__device__ __nv_bfloat16  g_h_hi[(size_t)SS * BB * HH];
__device__ __nv_bfloat16  g_h_lo[(size_t)SS * BB * HH];
__device__ __nv_bfloat16  g_x_hi[(size_t)SS * BB * II];
__device__ __nv_bfloat16  g_x_lo[(size_t)SS * BB * II];
__device__ float          g_c[BB * HH];

__device__ __nv_bfloat16 g_wih1_hi[G4 * II], g_wih1_lo[G4 * II];
__device__ __nv_bfloat16 g_whh1_hi[G4 * HH], g_whh1_lo[G4 * HH];
__device__ __nv_bfloat16 g_wih2_hi[G4 * HH], g_wih2_lo[G4 * HH];
__device__ __nv_bfloat16 g_whh2_hi[G4 * HH], g_whh2_lo[G4 * HH];
__device__ __nv_bfloat16 g_wih3_hi[G4 * HH], g_wih3_lo[G4 * HH];
__device__ __nv_bfloat16 g_whh3_hi[G4 * HH], g_whh3_lo[G4 * HH];

__device__ unsigned g_bar_count;
__device__ unsigned g_bar_gen;

// ---------------- helpers ----------------
__device__ __forceinline__ void split_bf16(float v, __nv_bfloat16& hi, __nv_bfloat16& lo) {
    hi = __float2bfloat16(v);
    lo = __float2bfloat16(v - __bfloat162float(hi));
}

__device__ __forceinline__ void mma16816(float* d, const unsigned* a, const unsigned* b) {
    asm volatile(
        "mma.sync.aligned.m16n8k16.row.col.f32.bf16.bf16.f32 "
        "{%0,%1,%2,%3}, {%4,%5,%6,%7}, {%8,%9}, {%0,%1,%2,%3};\n"
        : "+f"(d[0]), "+f"(d[1]), "+f"(d[2]), "+f"(d[3])
        : "r"(a[0]), "r"(a[1]), "r"(a[2]), "r"(a[3]), "r"(b[0]), "r"(b[1]));
}

__device__ __forceinline__ unsigned smem_u32(const void* p) {
    unsigned a;
    asm("{ .reg .u64 t; cvta.to.shared.u64 t, %1; cvt.u32.u64 %0, t; }" : "=r"(a) : "l"(p));
    return a;
}

__device__ __forceinline__ void cp16(unsigned dst, const void* src) {
    asm volatile("cp.async.cg.shared.global [%0], [%1], 16;" :: "r"(dst), "l"(src));
}

// software global barrier: all NCTA CTAs resident (1 CTA/SM via smem)
__device__ __forceinline__ void gbar(unsigned target) {
    __syncthreads();
    if (threadIdx.x == 0) {
        __threadfence();
        if (atomicAdd(&g_bar_count, 1u) == NCTA - 1) {
            g_bar_count = 0;
            __threadfence();
            atomicExch(&g_bar_gen, target);
        } else {
            unsigned g;
            do {
                asm volatile("ld.global.acquire.gpu.u32 %0, [%1];" : "=r"(g) : "l"(&g_bar_gen));
            } while (g < target);
        }
    }
    __syncthreads();
}

__global__ void k_bar_init() {
    g_bar_count = 0;
    g_bar_gen = 0;
}

// ---------------- weight / input split kernels ----------------
__global__ void k_split_w(const float* __restrict__ src, int sel, int n) {
    int i = blockIdx.x * blockDim.x + threadIdx.x;
    if (i >= n) return;
    __nv_bfloat16 *hi, *lo;
    switch (sel) {
        case 0: hi = g_wih1_hi; lo = g_wih1_lo; break;
        case 1: hi = g_whh1_hi; lo = g_whh1_lo; break;
        case 2: hi = g_wih2_hi; lo = g_wih2_lo; break;
        case 3: hi = g_whh2_hi; lo = g_whh2_lo; break;
        case 4: hi = g_wih3_hi; lo = g_wih3_lo; break;
        default: hi = g_whh3_hi; lo = g_whh3_lo; break;
    }
    split_bf16(src[i], hi[i], lo[i]);
}

__global__ void k_split_x(const float* __restrict__ x) {
    int i = blockIdx.x * blockDim.x + threadIdx.x;
    if (i >= SS * BB * II) return;
    int ii = i % II;
    int b  = (i / II) % BB;
    int s  = i / (II * BB);
    float v = x[((size_t)b * SS + s) * II + ii];
    split_bf16(v, g_x_hi[i], g_x_lo[i]);
}

// ---------------- xw GEMM: C[M=S*B, N=2048] = A[M,K] @ W[N,K]^T + bias ----------------
#define XBM 128
#define XBN 64
#define XBK 32

__global__ __launch_bounds__(256) void k_gemm_xw(int layer, const float* __restrict__ bias) {
    const __nv_bfloat16 *Ah, *Al, *Wh, *Wl;
    int K;
    if (layer == 0)      { Ah = g_x_hi; Al = g_x_lo; Wh = g_wih1_hi; Wl = g_wih1_lo; K = II; }
    else if (layer == 1) { Ah = g_h_hi; Al = g_h_lo; Wh = g_wih2_hi; Wl = g_wih2_lo; K = HH; }
    else                 { Ah = g_h_hi; Al = g_h_lo; Wh = g_wih3_hi; Wl = g_wih3_lo; K = HH; }

    __shared__ __nv_bfloat16 sAh[XBM][XBK + 2], sAl[XBM][XBK + 2];
    __shared__ __nv_bfloat16 sWh[XBN][XBK + 2], sWl[XBN][XBK + 2];

    int tid = threadIdx.x;
    int m0 = blockIdx.y * XBM;
    int n0 = blockIdx.x * XBN;
    int warp = tid >> 5, lane = tid & 31;
    int wm = warp >> 1, wn = warp & 1;
    int gq = lane >> 2, tg = lane & 3;

    float acc[2][4][4];
#pragma unroll
    for (int mi = 0; mi < 2; mi++)
#pragma unroll
        for (int ni = 0; ni < 4; ni++)
#pragma unroll
            for (int r = 0; r < 4; r++) acc[mi][ni][r] = 0.f;

    int nkt = K / XBK;
    for (int kt = 0; kt < nkt; kt++) {
        int k0 = kt * XBK;
        for (int v = tid; v < XBM * (XBK / 2); v += 256) {
            int r = v >> 4, c = (v & 15) * 2;
            size_t gi = (size_t)(m0 + r) * K + k0 + c;
            *(unsigned*)&sAh[r][c] = *(const unsigned*)&Ah[gi];
            *(unsigned*)&sAl[r][c] = *(const unsigned*)&Al[gi];
        }
        for (int v = tid; v < XBN * (XBK / 2); v += 256) {
            int r = v >> 4, c = (v & 15) * 2;
            size_t gi = (size_t)(n0 + r) * K + k0 + c;
            *(unsigned*)&sWh[r][c] = *(const unsigned*)&Wh[gi];
            *(unsigned*)&sWl[r][c] = *(const unsigned*)&Wl[gi];
        }
        __syncthreads();

#pragma unroll
        for (int kc = 0; kc < XBK; kc += 16) {
            unsigned ah[2][4], al[2][4], bh[4][2], bl[4][2];
#pragma unroll
            for (int mi = 0; mi < 2; mi++) {
                int r = wm * 32 + mi * 16 + gq;
                ah[mi][0] = *(unsigned*)&sAh[r][kc + 2 * tg];
                ah[mi][1] = *(unsigned*)&sAh[r + 8][kc + 2 * tg];
                ah[mi][2] = *(unsigned*)&sAh[r][kc + 2 * tg + 8];
                ah[mi][3] = *(unsigned*)&sAh[r + 8][kc + 2 * tg + 8];
                al[mi][0] = *(unsigned*)&sAl[r][kc + 2 * tg];
                al[mi][1] = *(unsigned*)&sAl[r + 8][kc + 2 * tg];
                al[mi][2] = *(unsigned*)&sAl[r][kc + 2 * tg + 8];
                al[mi][3] = *(unsigned*)&sAl[r + 8][kc + 2 * tg + 8];
            }
#pragma unroll
            for (int ni = 0; ni < 4; ni++) {
                int n = wn * 32 + ni * 8 + gq;
                bh[ni][0] = *(unsigned*)&sWh[n][kc + 2 * tg];
                bh[ni][1] = *(unsigned*)&sWh[n][kc + 2 * tg + 8];
                bl[ni][0] = *(unsigned*)&sWl[n][kc + 2 * tg];
                bl[ni][1] = *(unsigned*)&sWl[n][kc + 2 * tg + 8];
            }
#pragma unroll
            for (int mi = 0; mi < 2; mi++)
#pragma unroll
                for (int ni = 0; ni < 4; ni++) {
                    mma16816(acc[mi][ni], ah[mi], bh[ni]);
                    mma16816(acc[mi][ni], ah[mi], bl[ni]);
                    mma16816(acc[mi][ni], al[mi], bh[ni]);
                }
        }
        __syncthreads();
    }

#pragma unroll
    for (int mi = 0; mi < 2; mi++)
#pragma unroll
        for (int ni = 0; ni < 4; ni++) {
            int row = m0 + wm * 32 + mi * 16 + gq;
            int col = n0 + wn * 32 + ni * 8 + 2 * tg;
            float b0v = bias[col], b1v = bias[col + 1];
            g_xw[(size_t)row * G4 + col]           = acc[mi][ni][0] + b0v;
            g_xw[(size_t)row * G4 + col + 1]       = acc[mi][ni][1] + b1v;
            g_xw[(size_t)(row + 8) * G4 + col]     = acc[mi][ni][2] + b0v;
            g_xw[(size_t)(row + 8) * G4 + col + 1] = acc[mi][ni][3] + b1v;
        }
}

// ---------------- persistent recurrent kernel (one launch per layer) ----------------
// 128 CTAs: CTA = (batch block of 64) x (16 hidden units x 4 gates = 64 gate cols)
// W_hh slice (64 rows x 512, hi+lo) stays resident in SMEM for all 512 steps.
// SMEM layout (bytes):
//   0      : sWh [64][520] bf16  (66560)
//   66560  : sWl [64][520] bf16  (66560)
//   133120 : sHh [2][64][56] bf16 (14336)
//   147456 : sHl [2][64][56] bf16 (14336)
//   161792 : pre [64][65] float  (16640)
// total 178432
#define SMEM_REC 178432
#define SWP 520
#define SHP 56

__global__ __launch_bounds__(256, 1) void k_rec(int layer) {
    extern __shared__ char sm[];
    __nv_bfloat16 (*sWh)[SWP] = (__nv_bfloat16(*)[SWP])(sm);
    __nv_bfloat16 (*sWl)[SWP] = (__nv_bfloat16(*)[SWP])(sm + 66560);
    __nv_bfloat16* sHh = (__nv_bfloat16*)(sm + 133120);
    __nv_bfloat16* sHl = (__nv_bfloat16*)(sm + 147456);
    float (*pre)[65] = (float(*)[65])(sm + 161792);

    const __nv_bfloat16 *Whg, *Wlg;
    if (layer == 0)      { Whg = g_whh1_hi; Wlg = g_whh1_lo; }
    else if (layer == 1) { Whg = g_whh2_hi; Wlg = g_whh2_lo; }
    else                 { Whg = g_whh3_hi; Wlg = g_whh3_lo; }

    int tid = threadIdx.x;
    int warp = tid >> 5, lane = tid & 31;
    int bx = blockIdx.x;
    int bhid = bx >> 2;          // 0..31
    int bbat = bx & 3;           // 0..3
    int m0 = bbat * 64;
    int n0 = bhid * 16;
    int wm = warp >> 1, wn = warp & 1;
    int gq = lane >> 2, tg = lane & 3;

    // load resident weight slice: rows r=g*16+j -> global row g*512 + n0 + j
    for (int idx = tid; idx < 64 * 256; idx += 256) {
        int r = idx >> 8;
        int c = (idx & 255) * 2;
        int grow = (r >> 4) * HH + n0 + (r & 15);
        size_t gi = (size_t)grow * HH + c;
        *(unsigned*)&sWh[r][c] = *(const unsigned*)&Whg[gi];
        *(unsigned*)&sWl[r][c] = *(const unsigned*)&Wlg[gi];
    }
    __syncthreads();

    unsigned sHh_u = smem_u32(sHh);
    unsigned sHl_u = smem_u32(sHl);
    int prow = tid >> 2, pchk = tid & 3;   // cp.async: 16B per thread per buffer

    for (int s = 0; s < SS; s++) {
        float acc[4][4];
#pragma unroll
        for (int ni = 0; ni < 4; ni++)
#pragma unroll
            for (int r = 0; r < 4; r++) acc[ni][r] = 0.f;

        if (s > 0) {
            const __nv_bfloat16* Hh = g_h_hi + ((size_t)(s - 1) * BB + m0) * HH;
            const __nv_bfloat16* Hl = g_h_lo + ((size_t)(s - 1) * BB + m0) * HH;
            // prefetch tile 0 into buf 0
            {
                const __nv_bfloat16* gh = Hh + prow * HH + pchk * 8;
                const __nv_bfloat16* gl = Hl + prow * HH + pchk * 8;
                unsigned dh = sHh_u + (unsigned)((prow * SHP + pchk * 8) * 2);
                unsigned dl = sHl_u + (unsigned)((prow * SHP + pchk * 8) * 2);
                cp16(dh, gh);
                cp16(dl, gl);
                asm volatile("cp.async.commit_group;");
            }
            for (int kt = 0; kt < 16; kt++) {
                __syncthreads();   // everyone done with tile kt-1's buffer
                if (kt < 15) {
                    int nb = (kt + 1) & 1;
                    const __nv_bfloat16* gh = Hh + prow * HH + (kt + 1) * 32 + pchk * 8;
                    const __nv_bfloat16* gl = Hl + prow * HH + (kt + 1) * 32 + pchk * 8;
                    unsigned dh = sHh_u + (unsigned)((nb * 64 * SHP + prow * SHP + pchk * 8) * 2);
                    unsigned dl = sHl_u + (unsigned)((nb * 64 * SHP + prow * SHP + pchk * 8) * 2);
                    cp16(dh, gh);
                    cp16(dl, gl);
                    asm volatile("cp.async.commit_group;");
                    asm volatile("cp.async.wait_group 1;");
                } else {
                    asm volatile("cp.async.wait_group 0;");
                }
                __syncthreads();   // tile kt visible to all

                const __nv_bfloat16* cHh = sHh + (kt & 1) * 64 * SHP;
                const __nv_bfloat16* cHl = sHl + (kt & 1) * 64 * SHP;
#pragma unroll
                for (int kc = 0; kc < 32; kc += 16) {
                    int kw = kt * 32 + kc;
                    unsigned ah[4], al[4], bh[4][2], bl[4][2];
                    int r = wm * 16 + gq;
                    ah[0] = *(unsigned*)&cHh[r * SHP + kc + 2 * tg];
                    ah[1] = *(unsigned*)&cHh[(r + 8) * SHP + kc + 2 * tg];
                    ah[2] = *(unsigned*)&cHh[r * SHP + kc + 2 * tg + 8];
                    ah[3] = *(unsigned*)&cHh[(r + 8) * SHP + kc + 2 * tg + 8];
                    al[0] = *(unsigned*)&cHl[r * SHP + kc + 2 * tg];
                    al[1] = *(unsigned*)&cHl[(r + 8) * SHP + kc + 2 * tg];
                    al[2] = *(unsigned*)&cHl[r * SHP + kc + 2 * tg + 8];
                    al[3] = *(unsigned*)&cHl[(r + 8) * SHP + kc + 2 * tg + 8];
#pragma unroll
                    for (int ni = 0; ni < 4; ni++) {
                        int n = wn * 32 + ni * 8 + gq;
                        bh[ni][0] = *(unsigned*)&sWh[n][kw + 2 * tg];
                        bh[ni][1] = *(unsigned*)&sWh[n][kw + 2 * tg + 8];
                        bl[ni][0] = *(unsigned*)&sWl[n][kw + 2 * tg];
                        bl[ni][1] = *(unsigned*)&sWl[n][kw + 2 * tg + 8];
                    }
#pragma unroll
                    for (int ni = 0; ni < 4; ni++) {
                        mma16816(acc[ni], ah, bh[ni]);
                        mma16816(acc[ni], ah, bl[ni]);
                        mma16816(acc[ni], al, bh[ni]);
                    }
                }
            }
        }

        // pre-activations = acc + xw (xw already has bias)
        const float* xwrow = g_xw + ((size_t)s * BB + m0) * G4;
#pragma unroll
        for (int ni = 0; ni < 4; ni++) {
            int row = wm * 16 + gq;
            int col = wn * 32 + ni * 8 + 2 * tg;
            int gcol = (col >> 4) * HH + n0 + (col & 15);
            pre[row][col]         = acc[ni][0] + xwrow[(size_t)row * G4 + gcol];
            pre[row][col + 1]     = acc[ni][1] + xwrow[(size_t)row * G4 + gcol + 1];
            pre[row + 8][col]     = acc[ni][2] + xwrow[(size_t)(row + 8) * G4 + gcol];
            pre[row + 8][col + 1] = acc[ni][3] + xwrow[(size_t)(row + 8) * G4 + gcol + 1];
        }
        __syncthreads();

        // activations + state update (gate order i,f,g,o; elu cell/hidden)
        for (int idx = tid; idx < 64 * 16; idx += 256) {
            int r = idx >> 4, j = idx & 15;
            float pi = pre[r][j];
            float pf = pre[r][16 + j];
            float pg = pre[r][32 + j];
            float po = pre[r][48 + j];
            float iv = 1.f / (1.f + expf(-pi));
            float fv = 1.f / (1.f + expf(-pf));
            float gv = pg > 0.f ? pg : expm1f(pg);
            float ov = 1.f / (1.f + expf(-po));
            int cidx = (m0 + r) * HH + n0 + j;
            float cp = (s > 0) ? g_c[cidx] : 0.f;
            float cn = fv * cp + iv * gv;
            float hv = ov * (cn > 0.f ? cn : expm1f(cn));
            g_c[cidx] = cn;
            size_t hidx = ((size_t)s * BB + m0 + r) * HH + n0 + j;
            split_bf16(hv, g_h_hi[hidx], g_h_lo[hidx]);
        }

        gbar((unsigned)(s + 1));   // h_s visible chip-wide before step s+1
    }
}

// ---------------- final FC: out[b] = h[S-1,b,:] . fc_w + fc_b ----------------
__global__ void k_fc(const float* __restrict__ fcw, const float* __restrict__ fcb,
                     float* __restrict__ out) {
    __shared__ float red[4];
    int b = blockIdx.x, tid = threadIdx.x;
    size_t base = ((size_t)(SS - 1) * BB + b) * HH;
    float sum = 0.f;
    for (int j = tid; j < HH; j += 128)
        sum += (__bfloat162float(g_h_hi[base + j]) + __bfloat162float(g_h_lo[base + j])) * fcw[j];
#pragma unroll
    for (int o = 16; o; o >>= 1) sum += __shfl_xor_sync(0xFFFFFFFFu, sum, o);
    if ((tid & 31) == 0) red[tid >> 5] = sum;
    __syncthreads();
    if (tid == 0) out[b] = red[0] + red[1] + red[2] + red[3] + fcb[0];
}

// ---------------- launch ----------------
extern "C" void kernel_launch(void* const* d_in, const int* in_sizes, int n_in,
                              void* d_out, int out_size) {
    const float* x    = (const float*)d_in[0];
    const float* wih1 = (const float*)d_in[1];
    const float* whh1 = (const float*)d_in[2];
    const float* b1   = (const float*)d_in[3];
    const float* wih2 = (const float*)d_in[4];
    const float* whh2 = (const float*)d_in[5];
    const float* b2   = (const float*)d_in[6];
    const float* wih3 = (const float*)d_in[7];
    const float* whh3 = (const float*)d_in[8];
    const float* b3   = (const float*)d_in[9];
    const float* fcw  = (const float*)d_in[10];
    const float* fcb  = (const float*)d_in[11];

    cudaFuncSetAttribute(k_rec, cudaFuncAttributeMaxDynamicSharedMemorySize, SMEM_REC);

    k_split_w<<<(G4 * II + 255) / 256, 256>>>(wih1, 0, G4 * II);
    k_split_w<<<(G4 * HH + 255) / 256, 256>>>(whh1, 1, G4 * HH);
    k_split_w<<<(G4 * HH + 255) / 256, 256>>>(wih2, 2, G4 * HH);
    k_split_w<<<(G4 * HH + 255) / 256, 256>>>(whh2, 3, G4 * HH);
    k_split_w<<<(G4 * HH + 255) / 256, 256>>>(wih3, 4, G4 * HH);
    k_split_w<<<(G4 * HH + 255) / 256, 256>>>(whh3, 5, G4 * HH);
    k_split_x<<<(SS * BB * II + 255) / 256, 256>>>(x);

    const float* biases[3] = {b1, b2, b3};
    for (int L = 0; L < 3; L++) {
        dim3 gg(G4 / XBN, (SS * BB) / XBM);
        k_gemm_xw<<<gg, 256>>>(L, biases[L]);
        k_bar_init<<<1, 1>>>();
        k_rec<<<NCTA, 256, SMEM_REC>>>(L);
    }
    k_fc<<<BB, 128>>>(fcw, fcb, (float*)d_out);
}

// round 3
// speedup vs baseline: 1.1735x; 1.1735x over previous
#include <cuda_runtime.h>
#include <cuda_bf16.h>

#define SS 512
#define BB 256
#define II 64
#define HH 512
#define G4 2048
#define NCTA 128

// ---------------- static device scratch (no allocs allowed) ----------------
__device__ float          g_xw[(size_t)SS * BB * G4];      // 1 GB: per-layer input projection
__device__ __nv_bfloat16  g_h_hi[(size_t)SS * BB * HH];
__device__ __nv_bfloat16  g_h_lo[(size_t)SS * BB * HH];
__device__ __nv_bfloat16  g_x_hi[(size_t)SS * BB * II];
__device__ __nv_bfloat16  g_x_lo[(size_t)SS * BB * II];
__device__ float          g_c[BB * HH];

__device__ __nv_bfloat16 g_wih1_hi[G4 * II], g_wih1_lo[G4 * II];
__device__ __nv_bfloat16 g_whh1_hi[G4 * HH], g_whh1_lo[G4 * HH];
__device__ __nv_bfloat16 g_wih2_hi[G4 * HH], g_wih2_lo[G4 * HH];
__device__ __nv_bfloat16 g_whh2_hi[G4 * HH], g_whh2_lo[G4 * HH];
__device__ __nv_bfloat16 g_wih3_hi[G4 * HH], g_wih3_lo[G4 * HH];
__device__ __nv_bfloat16 g_whh3_hi[G4 * HH], g_whh3_lo[G4 * HH];

__device__ unsigned g_bar_count;
__device__ unsigned g_bar_gen;

// ---------------- helpers ----------------
__device__ __forceinline__ void split_bf16(float v, __nv_bfloat16& hi, __nv_bfloat16& lo) {
    hi = __float2bfloat16(v);
    lo = __float2bfloat16(v - __bfloat162float(hi));
}

__device__ __forceinline__ void mma16816(float* d, const unsigned* a, const unsigned* b) {
    asm volatile(
        "mma.sync.aligned.m16n8k16.row.col.f32.bf16.bf16.f32 "
        "{%0,%1,%2,%3}, {%4,%5,%6,%7}, {%8,%9}, {%0,%1,%2,%3};\n"
        : "+f"(d[0]), "+f"(d[1]), "+f"(d[2]), "+f"(d[3])
        : "r"(a[0]), "r"(a[1]), "r"(a[2]), "r"(a[3]), "r"(b[0]), "r"(b[1]));
}

__device__ __forceinline__ unsigned smem_u32(const void* p) {
    unsigned a;
    asm("{ .reg .u64 t; cvta.to.shared.u64 t, %1; cvt.u32.u64 %0, t; }" : "=r"(a) : "l"(p));
    return a;
}

__device__ __forceinline__ void cp16(unsigned dst, const void* src) {
    asm volatile("cp.async.cg.shared.global [%0], [%1], 16;" :: "r"(dst), "l"(src));
}
__device__ __forceinline__ void cp_commit() {
    asm volatile("cp.async.commit_group;");
}
template <int N>
__device__ __forceinline__ void cp_wait() {
    asm volatile("cp.async.wait_group %0;" :: "n"(N));
}

// software global barrier: all NCTA CTAs resident (1 CTA/SM via smem)
__device__ __forceinline__ void gbar(unsigned target) {
    __syncthreads();
    if (threadIdx.x == 0) {
        __threadfence();
        if (atomicAdd(&g_bar_count, 1u) == NCTA - 1) {
            g_bar_count = 0;
            __threadfence();
            atomicExch(&g_bar_gen, target);
        } else {
            unsigned g;
            do {
                asm volatile("ld.global.acquire.gpu.u32 %0, [%1];" : "=r"(g) : "l"(&g_bar_gen));
            } while (g < target);
        }
    }
    __syncthreads();
}

__global__ void k_bar_init() {
    g_bar_count = 0;
    g_bar_gen = 0;
}

// ---------------- weight / input split kernels ----------------
__global__ void k_split_w(const float* __restrict__ src, int sel, int n) {
    int i = blockIdx.x * blockDim.x + threadIdx.x;
    if (i >= n) return;
    __nv_bfloat16 *hi, *lo;
    switch (sel) {
        case 0: hi = g_wih1_hi; lo = g_wih1_lo; break;
        case 1: hi = g_whh1_hi; lo = g_whh1_lo; break;
        case 2: hi = g_wih2_hi; lo = g_wih2_lo; break;
        case 3: hi = g_whh2_hi; lo = g_whh2_lo; break;
        case 4: hi = g_wih3_hi; lo = g_wih3_lo; break;
        default: hi = g_whh3_hi; lo = g_whh3_lo; break;
    }
    split_bf16(src[i], hi[i], lo[i]);
}

__global__ void k_split_x(const float* __restrict__ x) {
    int i = blockIdx.x * blockDim.x + threadIdx.x;
    if (i >= SS * BB * II) return;
    int ii = i % II;
    int b  = (i / II) % BB;
    int s  = i / (II * BB);
    float v = x[((size_t)b * SS + s) * II + ii];
    split_bf16(v, g_x_hi[i], g_x_lo[i]);
}

// ---------------- xw GEMM: C[M=S*B, N=2048] = A[M,K] @ W[N,K]^T + bias --------
// 128x128x32 tiles, 4-stage cp.async pipeline, one __syncthreads per k-tile.
#define XBM 128
#define XBN 128
#define XBK 32
#define XST 4
#define XAP 40   // padded row length (elems); 80B rows, 16B aligned, conflict-free frags
#define XW_SMEM (XST * (XBM + XBN) * XAP * 2 * 2)   // 163840 bytes

__global__ __launch_bounds__(256) void k_gemm_xw(int layer, const float* __restrict__ bias) {
    const __nv_bfloat16 *Ah, *Al, *Wh, *Wl;
    int K;
    if (layer == 0)      { Ah = g_x_hi; Al = g_x_lo; Wh = g_wih1_hi; Wl = g_wih1_lo; K = II; }
    else if (layer == 1) { Ah = g_h_hi; Al = g_h_lo; Wh = g_wih2_hi; Wl = g_wih2_lo; K = HH; }
    else                 { Ah = g_h_hi; Al = g_h_lo; Wh = g_wih3_hi; Wl = g_wih3_lo; K = HH; }

    extern __shared__ char xsm[];
    __nv_bfloat16* sAh = (__nv_bfloat16*)xsm;                 // [XST][XBM][XAP]
    __nv_bfloat16* sAl = sAh + XST * XBM * XAP;
    __nv_bfloat16* sWh = sAl + XST * XBM * XAP;               // [XST][XBN][XAP]
    __nv_bfloat16* sWl = sWh + XST * XBN * XAP;

    unsigned uAh = smem_u32(sAh), uAl = smem_u32(sAl);
    unsigned uWh = smem_u32(sWh), uWl = smem_u32(sWl);

    int tid = threadIdx.x;
    int m0 = blockIdx.y * XBM;
    int n0 = blockIdx.x * XBN;
    int warp = tid >> 5, lane = tid & 31;
    int wm = warp >> 1, wn = warp & 1;      // 4 x 2 warp grid; warp tile 32 x 64
    int gq = lane >> 2, tg = lane & 3;

    int lrow = tid >> 1;                    // loader: 128 rows, 2 threads/row
    int lcol = (tid & 1) * 16;              // two 16B chunks at lcol, lcol+8

    float acc[2][8][4];
#pragma unroll
    for (int mi = 0; mi < 2; mi++)
#pragma unroll
        for (int ni = 0; ni < 8; ni++)
#pragma unroll
            for (int r = 0; r < 4; r++) acc[mi][ni][r] = 0.f;

    int nkt = K / XBK;

    // issue one k-tile into a stage
    auto issue = [&](int kt, int st) {
        size_t ga = (size_t)(m0 + lrow) * K + kt * XBK + lcol;
        size_t gw = (size_t)(n0 + lrow) * K + kt * XBK + lcol;
        unsigned da = (unsigned)(((st * XBM + lrow) * XAP + lcol) * 2);
        unsigned dw = (unsigned)(((st * XBN + lrow) * XAP + lcol) * 2);
        cp16(uAh + da, Ah + ga);       cp16(uAh + da + 16, Ah + ga + 8);
        cp16(uAl + da, Al + ga);       cp16(uAl + da + 16, Al + ga + 8);
        cp16(uWh + dw, Wh + gw);       cp16(uWh + dw + 16, Wh + gw + 8);
        cp16(uWl + dw, Wl + gw);       cp16(uWl + dw + 16, Wl + gw + 8);
        cp_commit();
    };

    int npro = nkt < (XST - 1) ? nkt : (XST - 1);
    for (int p = 0; p < npro; p++) issue(p, p);

    for (int kt = 0; kt < nkt; kt++) {
        int rem = nkt - kt - 1;          // groups that must stay pending after wait
        if (rem >= 2) cp_wait<2>();
        else if (rem == 1) cp_wait<1>();
        else cp_wait<0>();
        __syncthreads();                 // tile kt visible; everyone done with kt-1

        if (kt + XST - 1 < nkt) issue(kt + XST - 1, (kt + XST - 1) % XST);

        int st = kt % XST;
        const __nv_bfloat16* cAh = sAh + st * XBM * XAP;
        const __nv_bfloat16* cAl = sAl + st * XBM * XAP;
        const __nv_bfloat16* cWh = sWh + st * XBN * XAP;
        const __nv_bfloat16* cWl = sWl + st * XBN * XAP;

#pragma unroll
        for (int kc = 0; kc < XBK; kc += 16) {
            unsigned ah[2][4], al[2][4], bh[8][2], bl[8][2];
#pragma unroll
            for (int mi = 0; mi < 2; mi++) {
                int r = wm * 32 + mi * 16 + gq;
                ah[mi][0] = *(unsigned*)&cAh[r * XAP + kc + 2 * tg];
                ah[mi][1] = *(unsigned*)&cAh[(r + 8) * XAP + kc + 2 * tg];
                ah[mi][2] = *(unsigned*)&cAh[r * XAP + kc + 2 * tg + 8];
                ah[mi][3] = *(unsigned*)&cAh[(r + 8) * XAP + kc + 2 * tg + 8];
                al[mi][0] = *(unsigned*)&cAl[r * XAP + kc + 2 * tg];
                al[mi][1] = *(unsigned*)&cAl[(r + 8) * XAP + kc + 2 * tg];
                al[mi][2] = *(unsigned*)&cAl[r * XAP + kc + 2 * tg + 8];
                al[mi][3] = *(unsigned*)&cAl[(r + 8) * XAP + kc + 2 * tg + 8];
            }
#pragma unroll
            for (int ni = 0; ni < 8; ni++) {
                int n = wn * 64 + ni * 8 + gq;
                bh[ni][0] = *(unsigned*)&cWh[n * XAP + kc + 2 * tg];
                bh[ni][1] = *(unsigned*)&cWh[n * XAP + kc + 2 * tg + 8];
                bl[ni][0] = *(unsigned*)&cWl[n * XAP + kc + 2 * tg];
                bl[ni][1] = *(unsigned*)&cWl[n * XAP + kc + 2 * tg + 8];
            }
#pragma unroll
            for (int mi = 0; mi < 2; mi++)
#pragma unroll
                for (int ni = 0; ni < 8; ni++) {
                    mma16816(acc[mi][ni], ah[mi], bh[ni]);
                    mma16816(acc[mi][ni], ah[mi], bl[ni]);
                    mma16816(acc[mi][ni], al[mi], bh[ni]);
                }
        }
    }

#pragma unroll
    for (int mi = 0; mi < 2; mi++)
#pragma unroll
        for (int ni = 0; ni < 8; ni++) {
            int row = m0 + wm * 32 + mi * 16 + gq;
            int col = n0 + wn * 64 + ni * 8 + 2 * tg;
            float b0v = bias[col], b1v = bias[col + 1];
            g_xw[(size_t)row * G4 + col]           = acc[mi][ni][0] + b0v;
            g_xw[(size_t)row * G4 + col + 1]       = acc[mi][ni][1] + b1v;
            g_xw[(size_t)(row + 8) * G4 + col]     = acc[mi][ni][2] + b0v;
            g_xw[(size_t)(row + 8) * G4 + col + 1] = acc[mi][ni][3] + b1v;
        }
}

// ---------------- persistent recurrent kernel (one launch per layer) ----------------
// 128 CTAs: CTA = (batch block of 64) x (16 hidden units x 4 gates = 64 gate cols)
// W_hh slice resident in SMEM; h streamed in 64-wide k-tiles, double-buffered cp.async.
// SMEM layout (bytes):
//   0      : sWh [64][520] bf16          (66560)
//   66560  : sWl [64][520] bf16          (66560)
//   133120 : sHh [2][64][72] bf16        (18432)
//   151552 : sHl [2][64][72] bf16        (18432)
//   169984 : pre [64][65] float          (16640)
// total 186624
#define SMEM_REC 186624
#define SWP 520
#define SHP 72
#define RKT 64    // k-tile width

__global__ __launch_bounds__(256, 1) void k_rec(int layer) {
    extern __shared__ char sm[];
    __nv_bfloat16 (*sWh)[SWP] = (__nv_bfloat16(*)[SWP])(sm);
    __nv_bfloat16 (*sWl)[SWP] = (__nv_bfloat16(*)[SWP])(sm + 66560);
    __nv_bfloat16* sHh = (__nv_bfloat16*)(sm + 133120);
    __nv_bfloat16* sHl = (__nv_bfloat16*)(sm + 151552);
    float (*pre)[65] = (float(*)[65])(sm + 169984);

    const __nv_bfloat16 *Whg, *Wlg;
    if (layer == 0)      { Whg = g_whh1_hi; Wlg = g_whh1_lo; }
    else if (layer == 1) { Whg = g_whh2_hi; Wlg = g_whh2_lo; }
    else                 { Whg = g_whh3_hi; Wlg = g_whh3_lo; }

    int tid = threadIdx.x;
    int warp = tid >> 5, lane = tid & 31;
    int bx = blockIdx.x;
    int bhid = bx >> 2;          // 0..31
    int bbat = bx & 3;           // 0..3
    int m0 = bbat * 64;
    int n0 = bhid * 16;
    int wm = warp >> 1, wn = warp & 1;
    int gq = lane >> 2, tg = lane & 3;

    // load resident weight slice: rows r=g*16+j -> global row g*512 + n0 + j
    for (int idx = tid; idx < 64 * 256; idx += 256) {
        int r = idx >> 8;
        int c = (idx & 255) * 2;
        int grow = (r >> 4) * HH + n0 + (r & 15);
        size_t gi = (size_t)grow * HH + c;
        *(unsigned*)&sWh[r][c] = *(const unsigned*)&Whg[gi];
        *(unsigned*)&sWl[r][c] = *(const unsigned*)&Wlg[gi];
    }
    __syncthreads();

    unsigned uHh = smem_u32(sHh);
    unsigned uHl = smem_u32(sHl);
    int lrow = tid >> 2;              // 64 rows, 4 threads/row
    int lcol = (tid & 3) * 16;        // chunks at lcol, lcol+8 (covers 64 cols)

    for (int s = 0; s < SS; s++) {
        float acc[4][4];
#pragma unroll
        for (int ni = 0; ni < 4; ni++)
#pragma unroll
            for (int r = 0; r < 4; r++) acc[ni][r] = 0.f;

        if (s > 0) {
            const __nv_bfloat16* Hh = g_h_hi + ((size_t)(s - 1) * BB + m0) * HH;
            const __nv_bfloat16* Hl = g_h_lo + ((size_t)(s - 1) * BB + m0) * HH;

            auto issueH = [&](int kt) {
                int b = kt & 1;
                const __nv_bfloat16* gh = Hh + lrow * HH + kt * RKT + lcol;
                const __nv_bfloat16* gl = Hl + lrow * HH + kt * RKT + lcol;
                unsigned d = (unsigned)(((b * 64 + lrow) * SHP + lcol) * 2);
                cp16(uHh + d, gh);  cp16(uHh + d + 16, gh + 8);
                cp16(uHl + d, gl);  cp16(uHl + d + 16, gl + 8);
                cp_commit();
            };

            issueH(0);
            for (int kt = 0; kt < HH / RKT; kt++) {
                cp_wait<0>();        // tile kt arrived
                __syncthreads();     // visible; everyone done with tile kt-1's buffer
                if (kt + 1 < HH / RKT) issueH(kt + 1);

                int b = kt & 1;
                const __nv_bfloat16* cHh = sHh + b * 64 * SHP;
                const __nv_bfloat16* cHl = sHl + b * 64 * SHP;
#pragma unroll
                for (int kc = 0; kc < RKT; kc += 16) {
                    int kw = kt * RKT + kc;
                    unsigned ah[4], al[4], bh[4][2], bl[4][2];
                    int r = wm * 16 + gq;
                    ah[0] = *(unsigned*)&cHh[r * SHP + kc + 2 * tg];
                    ah[1] = *(unsigned*)&cHh[(r + 8) * SHP + kc + 2 * tg];
                    ah[2] = *(unsigned*)&cHh[r * SHP + kc + 2 * tg + 8];
                    ah[3] = *(unsigned*)&cHh[(r + 8) * SHP + kc + 2 * tg + 8];
                    al[0] = *(unsigned*)&cHl[r * SHP + kc + 2 * tg];
                    al[1] = *(unsigned*)&cHl[(r + 8) * SHP + kc + 2 * tg];
                    al[2] = *(unsigned*)&cHl[r * SHP + kc + 2 * tg + 8];
                    al[3] = *(unsigned*)&cHl[(r + 8) * SHP + kc + 2 * tg + 8];
#pragma unroll
                    for (int ni = 0; ni < 4; ni++) {
                        int n = wn * 32 + ni * 8 + gq;
                        bh[ni][0] = *(unsigned*)&sWh[n][kw + 2 * tg];
                        bh[ni][1] = *(unsigned*)&sWh[n][kw + 2 * tg + 8];
                        bl[ni][0] = *(unsigned*)&sWl[n][kw + 2 * tg];
                        bl[ni][1] = *(unsigned*)&sWl[n][kw + 2 * tg + 8];
                    }
#pragma unroll
                    for (int ni = 0; ni < 4; ni++) {
                        mma16816(acc[ni], ah, bh[ni]);
                        mma16816(acc[ni], ah, bl[ni]);
                        mma16816(acc[ni], al, bh[ni]);
                    }
                }
            }
        }

        // pre-activations = acc + xw (xw already has bias)
        const float* xwrow = g_xw + ((size_t)s * BB + m0) * G4;
#pragma unroll
        for (int ni = 0; ni < 4; ni++) {
            int row = wm * 16 + gq;
            int col = wn * 32 + ni * 8 + 2 * tg;
            int gcol = (col >> 4) * HH + n0 + (col & 15);
            pre[row][col]         = acc[ni][0] + xwrow[(size_t)row * G4 + gcol];
            pre[row][col + 1]     = acc[ni][1] + xwrow[(size_t)row * G4 + gcol + 1];
            pre[row + 8][col]     = acc[ni][2] + xwrow[(size_t)(row + 8) * G4 + gcol];
            pre[row + 8][col + 1] = acc[ni][3] + xwrow[(size_t)(row + 8) * G4 + gcol + 1];
        }
        __syncthreads();

        // activations + state update (gate order i,f,g,o; elu cell/hidden)
        for (int idx = tid; idx < 64 * 16; idx += 256) {
            int r = idx >> 4, j = idx & 15;
            float pi = pre[r][j];
            float pf = pre[r][16 + j];
            float pg = pre[r][32 + j];
            float po = pre[r][48 + j];
            float iv = 1.f / (1.f + expf(-pi));
            float fv = 1.f / (1.f + expf(-pf));
            float gv = pg > 0.f ? pg : expm1f(pg);
            float ov = 1.f / (1.f + expf(-po));
            int cidx = (m0 + r) * HH + n0 + j;
            float cp = (s > 0) ? g_c[cidx] : 0.f;
            float cn = fv * cp + iv * gv;
            float hv = ov * (cn > 0.f ? cn : expm1f(cn));
            g_c[cidx] = cn;
            size_t hidx = ((size_t)s * BB + m0 + r) * HH + n0 + j;
            split_bf16(hv, g_h_hi[hidx], g_h_lo[hidx]);
        }

        gbar((unsigned)(s + 1));   // h_s visible chip-wide before step s+1
    }
}

// ---------------- final FC: out[b] = h[S-1,b,:] . fc_w + fc_b ----------------
__global__ void k_fc(const float* __restrict__ fcw, const float* __restrict__ fcb,
                     float* __restrict__ out) {
    __shared__ float red[4];
    int b = blockIdx.x, tid = threadIdx.x;
    size_t base = ((size_t)(SS - 1) * BB + b) * HH;
    float sum = 0.f;
    for (int j = tid; j < HH; j += 128)
        sum += (__bfloat162float(g_h_hi[base + j]) + __bfloat162float(g_h_lo[base + j])) * fcw[j];
#pragma unroll
    for (int o = 16; o; o >>= 1) sum += __shfl_xor_sync(0xFFFFFFFFu, sum, o);
    if ((tid & 31) == 0) red[tid >> 5] = sum;
    __syncthreads();
    if (tid == 0) out[b] = red[0] + red[1] + red[2] + red[3] + fcb[0];
}

// ---------------- launch ----------------
extern "C" void kernel_launch(void* const* d_in, const int* in_sizes, int n_in,
                              void* d_out, int out_size) {
    const float* x    = (const float*)d_in[0];
    const float* wih1 = (const float*)d_in[1];
    const float* whh1 = (const float*)d_in[2];
    const float* b1   = (const float*)d_in[3];
    const float* wih2 = (const float*)d_in[4];
    const float* whh2 = (const float*)d_in[5];
    const float* b2   = (const float*)d_in[6];
    const float* wih3 = (const float*)d_in[7];
    const float* whh3 = (const float*)d_in[8];
    const float* b3   = (const float*)d_in[9];
    const float* fcw  = (const float*)d_in[10];
    const float* fcb  = (const float*)d_in[11];

    cudaFuncSetAttribute(k_rec, cudaFuncAttributeMaxDynamicSharedMemorySize, SMEM_REC);
    cudaFuncSetAttribute(k_gemm_xw, cudaFuncAttributeMaxDynamicSharedMemorySize, XW_SMEM);

    k_split_w<<<(G4 * II + 255) / 256, 256>>>(wih1, 0, G4 * II);
    k_split_w<<<(G4 * HH + 255) / 256, 256>>>(whh1, 1, G4 * HH);
    k_split_w<<<(G4 * HH + 255) / 256, 256>>>(wih2, 2, G4 * HH);
    k_split_w<<<(G4 * HH + 255) / 256, 256>>>(whh2, 3, G4 * HH);
    k_split_w<<<(G4 * HH + 255) / 256, 256>>>(wih3, 4, G4 * HH);
    k_split_w<<<(G4 * HH + 255) / 256, 256>>>(whh3, 5, G4 * HH);
    k_split_x<<<(SS * BB * II + 255) / 256, 256>>>(x);

    const float* biases[3] = {b1, b2, b3};
    for (int L = 0; L < 3; L++) {
        dim3 gg(G4 / XBN, (SS * BB) / XBM);
        k_gemm_xw<<<gg, 256, XW_SMEM>>>(L, biases[L]);
        k_bar_init<<<1, 1>>>();
        k_rec<<<NCTA, 256, SMEM_REC>>>(L);
    }
    k_fc<<<BB, 128>>>(fcw, fcb, (float*)d_out);
}

// round 5
// speedup vs baseline: 1.3092x; 1.1156x over previous
#include <cuda_runtime.h>
#include <cuda_bf16.h>
#include <cstdint>

#define SS 512
#define BB 256
#define II 64
#define HH 512
#define G4 2048
#define NCTA 128

// ---------------- static device scratch (no allocs allowed) ----------------
__device__ float          g_xw[(size_t)SS * BB * G4];      // 1 GB: per-layer input projection
__device__ __nv_bfloat16  g_h_hi[(size_t)SS * BB * HH];
__device__ __nv_bfloat16  g_h_lo[(size_t)SS * BB * HH];
__device__ __nv_bfloat16  g_x_hi[(size_t)SS * BB * II];
__device__ __nv_bfloat16  g_x_lo[(size_t)SS * BB * II];
__device__ float          g_c[BB * HH];

__device__ __nv_bfloat16 g_wih1_hi[G4 * II], g_wih1_lo[G4 * II];
__device__ __nv_bfloat16 g_whh1_hi[G4 * HH], g_whh1_lo[G4 * HH];
__device__ __nv_bfloat16 g_wih2_hi[G4 * HH], g_wih2_lo[G4 * HH];
__device__ __nv_bfloat16 g_whh2_hi[G4 * HH], g_whh2_lo[G4 * HH];
__device__ __nv_bfloat16 g_wih3_hi[G4 * HH], g_wih3_lo[G4 * HH];
__device__ __nv_bfloat16 g_whh3_hi[G4 * HH], g_whh3_lo[G4 * HH];

// per-batch-group barriers: 4 groups x 32 CTAs, each counter/gen on its own 128B line
__device__ unsigned g_bcnt[4 * 32];
__device__ unsigned g_bgen[4 * 32];

// ---------------- helpers ----------------
__device__ __forceinline__ void split_bf16(float v, __nv_bfloat16& hi, __nv_bfloat16& lo) {
    hi = __float2bfloat16(v);
    lo = __float2bfloat16(v - __bfloat162float(hi));
}

__device__ __forceinline__ void mma16816(float* d, const unsigned* a, const unsigned* b) {
    asm volatile(
        "mma.sync.aligned.m16n8k16.row.col.f32.bf16.bf16.f32 "
        "{%0,%1,%2,%3}, {%4,%5,%6,%7}, {%8,%9}, {%0,%1,%2,%3};\n"
        : "+f"(d[0]), "+f"(d[1]), "+f"(d[2]), "+f"(d[3])
        : "r"(a[0]), "r"(a[1]), "r"(a[2]), "r"(a[3]), "r"(b[0]), "r"(b[1]));
}

__device__ __forceinline__ unsigned smem_u32(const void* p) {
    unsigned a;
    asm("{ .reg .u64 t; cvta.to.shared.u64 t, %1; cvt.u32.u64 %0, t; }" : "=r"(a) : "l"(p));
    return a;
}

__device__ __forceinline__ void cp16(unsigned dst, const void* src) {
    asm volatile("cp.async.cg.shared.global [%0], [%1], 16;" :: "r"(dst), "l"(src));
}
__device__ __forceinline__ void cp_commit() {
    asm volatile("cp.async.commit_group;");
}
template <int N>
__device__ __forceinline__ void cp_wait() {
    asm volatile("cp.async.wait_group %0;" :: "n"(N));
}

__device__ __forceinline__ float fsigmoid(float x) {
    return 1.f / (1.f + __expf(-x));
}
__device__ __forceinline__ float felu(float x) {
    return x > 0.f ? x : (__expf(x) - 1.f);
}

// group barrier: 32 CTAs of one batch group
__device__ __forceinline__ void gbar_g(unsigned target, int grp) {
    __syncthreads();
    if (threadIdx.x == 0) {
        unsigned* cnt = &g_bcnt[grp * 32];
        unsigned* gen = &g_bgen[grp * 32];
        __threadfence();
        if (atomicAdd(cnt, 1u) == 31u) {
            *cnt = 0;
            __threadfence();
            atomicExch(gen, target);
        } else {
            unsigned g;
            do {
                asm volatile("ld.global.acquire.gpu.u32 %0, [%1];" : "=r"(g) : "l"(gen));
            } while (g < target);
        }
    }
    __syncthreads();
}

__global__ void k_bar_init() {
    int i = threadIdx.x;
    if (i < 4 * 32) { g_bcnt[i] = 0; g_bgen[i] = 0; }
}

// ---------------- weight / input split kernels ----------------
__global__ void k_split_w(const float* __restrict__ src, int sel, int n) {
    int i = blockIdx.x * blockDim.x + threadIdx.x;
    if (i >= n) return;
    __nv_bfloat16 *hi, *lo;
    switch (sel) {
        case 0: hi = g_wih1_hi; lo = g_wih1_lo; break;
        case 1: hi = g_whh1_hi; lo = g_whh1_lo; break;
        case 2: hi = g_wih2_hi; lo = g_wih2_lo; break;
        case 3: hi = g_whh2_hi; lo = g_whh2_lo; break;
        case 4: hi = g_wih3_hi; lo = g_wih3_lo; break;
        default: hi = g_whh3_hi; lo = g_whh3_lo; break;
    }
    split_bf16(src[i], hi[i], lo[i]);
}

__global__ void k_split_x(const float* __restrict__ x) {
    int i = blockIdx.x * blockDim.x + threadIdx.x;
    if (i >= SS * BB * II) return;
    int ii = i % II;
    int b  = (i / II) % BB;
    int s  = i / (II * BB);
    float v = x[((size_t)b * SS + s) * II + ii];
    split_bf16(v, g_x_hi[i], g_x_lo[i]);
}

// ---------------- xw GEMM: C[M=S*B, N=2048] = A[M,K] @ W[N,K]^T + bias --------
// 128x128x32 tiles, 4-stage cp.async pipeline, one __syncthreads per k-tile.
#define XBM 128
#define XBN 128
#define XBK 32
#define XST 4
#define XAP 40
#define XW_SMEM (XST * (XBM + XBN) * XAP * 2 * 2)   // 163840 bytes

__global__ __launch_bounds__(256) void k_gemm_xw(int layer, const float* __restrict__ bias) {
    const __nv_bfloat16 *Ah, *Al, *Wh, *Wl;
    int K;
    if (layer == 0)      { Ah = g_x_hi; Al = g_x_lo; Wh = g_wih1_hi; Wl = g_wih1_lo; K = II; }
    else if (layer == 1) { Ah = g_h_hi; Al = g_h_lo; Wh = g_wih2_hi; Wl = g_wih2_lo; K = HH; }
    else                 { Ah = g_h_hi; Al = g_h_lo; Wh = g_wih3_hi; Wl = g_wih3_lo; K = HH; }

    extern __shared__ char xsm[];
    __nv_bfloat16* sAh = (__nv_bfloat16*)xsm;
    __nv_bfloat16* sAl = sAh + XST * XBM * XAP;
    __nv_bfloat16* sWh = sAl + XST * XBM * XAP;
    __nv_bfloat16* sWl = sWh + XST * XBN * XAP;

    unsigned uAh = smem_u32(sAh), uAl = smem_u32(sAl);
    unsigned uWh = smem_u32(sWh), uWl = smem_u32(sWl);

    int tid = threadIdx.x;
    int m0 = blockIdx.y * XBM;
    int n0 = blockIdx.x * XBN;
    int warp = tid >> 5, lane = tid & 31;
    int wm = warp >> 1, wn = warp & 1;
    int gq = lane >> 2, tg = lane & 3;

    int lrow = tid >> 1;
    int lcol = (tid & 1) * 16;

    float acc[2][8][4];
#pragma unroll
    for (int mi = 0; mi < 2; mi++)
#pragma unroll
        for (int ni = 0; ni < 8; ni++)
#pragma unroll
            for (int r = 0; r < 4; r++) acc[mi][ni][r] = 0.f;

    int nkt = K / XBK;

    auto issue = [&](int kt, int st) {
        size_t ga = (size_t)(m0 + lrow) * K + kt * XBK + lcol;
        size_t gw = (size_t)(n0 + lrow) * K + kt * XBK + lcol;
        unsigned da = (unsigned)(((st * XBM + lrow) * XAP + lcol) * 2);
        unsigned dw = (unsigned)(((st * XBN + lrow) * XAP + lcol) * 2);
        cp16(uAh + da, Ah + ga);       cp16(uAh + da + 16, Ah + ga + 8);
        cp16(uAl + da, Al + ga);       cp16(uAl + da + 16, Al + ga + 8);
        cp16(uWh + dw, Wh + gw);       cp16(uWh + dw + 16, Wh + gw + 8);
        cp16(uWl + dw, Wl + gw);       cp16(uWl + dw + 16, Wl + gw + 8);
        cp_commit();
    };

    int npro = nkt < (XST - 1) ? nkt : (XST - 1);
    for (int p = 0; p < npro; p++) issue(p, p);

    for (int kt = 0; kt < nkt; kt++) {
        int rem = nkt - kt - 1;
        if (rem >= 2) cp_wait<2>();
        else if (rem == 1) cp_wait<1>();
        else cp_wait<0>();
        __syncthreads();

        if (kt + XST - 1 < nkt) issue(kt + XST - 1, (kt + XST - 1) % XST);

        int st = kt % XST;
        const __nv_bfloat16* cAh = sAh + st * XBM * XAP;
        const __nv_bfloat16* cAl = sAl + st * XBM * XAP;
        const __nv_bfloat16* cWh = sWh + st * XBN * XAP;
        const __nv_bfloat16* cWl = sWl + st * XBN * XAP;

#pragma unroll
        for (int kc = 0; kc < XBK; kc += 16) {
            unsigned ah[2][4], al[2][4], bh[8][2], bl[8][2];
#pragma unroll
            for (int mi = 0; mi < 2; mi++) {
                int r = wm * 32 + mi * 16 + gq;
                ah[mi][0] = *(unsigned*)&cAh[r * XAP + kc + 2 * tg];
                ah[mi][1] = *(unsigned*)&cAh[(r + 8) * XAP + kc + 2 * tg];
                ah[mi][2] = *(unsigned*)&cAh[r * XAP + kc + 2 * tg + 8];
                ah[mi][3] = *(unsigned*)&cAh[(r + 8) * XAP + kc + 2 * tg + 8];
                al[mi][0] = *(unsigned*)&cAl[r * XAP + kc + 2 * tg];
                al[mi][1] = *(unsigned*)&cAl[(r + 8) * XAP + kc + 2 * tg];
                al[mi][2] = *(unsigned*)&cAl[r * XAP + kc + 2 * tg + 8];
                al[mi][3] = *(unsigned*)&cAl[(r + 8) * XAP + kc + 2 * tg + 8];
            }
#pragma unroll
            for (int ni = 0; ni < 8; ni++) {
                int n = wn * 64 + ni * 8 + gq;
                bh[ni][0] = *(unsigned*)&cWh[n * XAP + kc + 2 * tg];
                bh[ni][1] = *(unsigned*)&cWh[n * XAP + kc + 2 * tg + 8];
                bl[ni][0] = *(unsigned*)&cWl[n * XAP + kc + 2 * tg];
                bl[ni][1] = *(unsigned*)&cWl[n * XAP + kc + 2 * tg + 8];
            }
#pragma unroll
            for (int mi = 0; mi < 2; mi++)
#pragma unroll
                for (int ni = 0; ni < 8; ni++) {
                    mma16816(acc[mi][ni], ah[mi], bh[ni]);
                    mma16816(acc[mi][ni], ah[mi], bl[ni]);
                    mma16816(acc[mi][ni], al[mi], bh[ni]);
                }
        }
    }

#pragma unroll
    for (int mi = 0; mi < 2; mi++)
#pragma unroll
        for (int ni = 0; ni < 8; ni++) {
            int row = m0 + wm * 32 + mi * 16 + gq;
            int col = n0 + wn * 64 + ni * 8 + 2 * tg;
            float b0v = bias[col], b1v = bias[col + 1];
            g_xw[(size_t)row * G4 + col]           = acc[mi][ni][0] + b0v;
            g_xw[(size_t)row * G4 + col + 1]       = acc[mi][ni][1] + b1v;
            g_xw[(size_t)(row + 8) * G4 + col]     = acc[mi][ni][2] + b0v;
            g_xw[(size_t)(row + 8) * G4 + col + 1] = acc[mi][ni][3] + b1v;
        }
}

// ---------------- persistent recurrent kernel (one launch per layer) ----------------
// 128 CTAs: CTA = (batch block of 64) x (16 hidden units x 4 gates = 64 gate cols)
// Warp tiling is GATE-ALIGNED: warp (wm, wn) computes rows wm*16..+15 and, for each
// gate g, cols g*16 + wn*8 .. +7. Thread (gq, tg) therefore holds i,f,g,o for the
// same (row, hidden j) -> epilogue entirely in registers (no pre[][] SMEM).
// SMEM layout (bytes):
//   0      : sWh [64][520] bf16          (66560)
//   66560  : sWl [64][520] bf16          (66560)
//   133120 : sHh [2][64][72] bf16        (18432)
//   151552 : sHl [2][64][72] bf16        (18432)
// total 169984
#define SMEM_REC 169984
#define SWP 520
#define SHP 72
#define RKT 64    // k-tile width

__global__ __launch_bounds__(256, 1) void k_rec(int layer) {
    extern __shared__ char sm[];
    __nv_bfloat16 (*sWh)[SWP] = (__nv_bfloat16(*)[SWP])(sm);
    __nv_bfloat16 (*sWl)[SWP] = (__nv_bfloat16(*)[SWP])(sm + 66560);
    __nv_bfloat16* sHh = (__nv_bfloat16*)(sm + 133120);
    __nv_bfloat16* sHl = (__nv_bfloat16*)(sm + 151552);

    const __nv_bfloat16 *Whg, *Wlg;
    if (layer == 0)      { Whg = g_whh1_hi; Wlg = g_whh1_lo; }
    else if (layer == 1) { Whg = g_whh2_hi; Wlg = g_whh2_lo; }
    else                 { Whg = g_whh3_hi; Wlg = g_whh3_lo; }

    int tid = threadIdx.x;
    int warp = tid >> 5, lane = tid & 31;
    int bx = blockIdx.x;
    int bhid = bx >> 2;          // 0..31
    int bbat = bx & 3;           // 0..3  (barrier group)
    int m0 = bbat * 64;
    int n0 = bhid * 16;
    int wm = warp >> 1, wn = warp & 1;
    int gq = lane >> 2, tg = lane & 3;

    // load resident weight slice: local row r = g*16 + j -> global row g*512 + n0 + j
    for (int idx = tid; idx < 64 * 256; idx += 256) {
        int r = idx >> 8;
        int c = (idx & 255) * 2;
        int grow = (r >> 4) * HH + n0 + (r & 15);
        size_t gi = (size_t)grow * HH + c;
        *(unsigned*)&sWh[r][c] = *(const unsigned*)&Whg[gi];
        *(unsigned*)&sWl[r][c] = *(const unsigned*)&Wlg[gi];
    }
    __syncthreads();

    unsigned uHh = smem_u32(sHh);
    unsigned uHl = smem_u32(sHl);
    int lrow = tid >> 2;              // 64 rows, 4 threads/row
    int lcol = (tid & 3) * 16;        // chunks at lcol, lcol+8 (covers 64 cols)

    // per-thread output coordinates (gate-aligned)
    int row0 = wm * 16 + gq;          // local batch rows row0, row0+8
    int jloc = wn * 8 + 2 * tg;       // local hidden col (0..15), this thread owns jloc, jloc+1

    for (int s = 0; s < SS; s++) {
        // ---- prefetch xw and c for this thread's 4 cells (overlaps MMA loop) ----
        float xwf[4][2][2];           // [gate][rr][cc]
        float cb[2][2];
        {
            const float* xwb = g_xw + ((size_t)s * BB + m0 + row0) * G4;
#pragma unroll
            for (int g = 0; g < 4; g++)
#pragma unroll
                for (int rr = 0; rr < 2; rr++) {
                    float2 v = *(const float2*)(xwb + (size_t)rr * 8 * G4 + g * HH + n0 + jloc);
                    xwf[g][rr][0] = v.x; xwf[g][rr][1] = v.y;
                }
            if (s > 0) {
#pragma unroll
                for (int rr = 0; rr < 2; rr++) {
                    float2 v = *(const float2*)(g_c + (size_t)(m0 + row0 + rr * 8) * HH + n0 + jloc);
                    cb[rr][0] = v.x; cb[rr][1] = v.y;
                }
            } else {
                cb[0][0] = cb[0][1] = cb[1][0] = cb[1][1] = 0.f;
            }
        }

        float acc[4][4];              // [gate][frag]
#pragma unroll
        for (int g = 0; g < 4; g++)
#pragma unroll
            for (int r = 0; r < 4; r++) acc[g][r] = 0.f;

        if (s > 0) {
            const __nv_bfloat16* Hh = g_h_hi + ((size_t)(s - 1) * BB + m0) * HH;
            const __nv_bfloat16* Hl = g_h_lo + ((size_t)(s - 1) * BB + m0) * HH;

            auto issueH = [&](int kt) {
                int b = kt & 1;
                const __nv_bfloat16* gh = Hh + lrow * HH + kt * RKT + lcol;
                const __nv_bfloat16* gl = Hl + lrow * HH + kt * RKT + lcol;
                unsigned d = (unsigned)(((b * 64 + lrow) * SHP + lcol) * 2);
                cp16(uHh + d, gh);  cp16(uHh + d + 16, gh + 8);
                cp16(uHl + d, gl);  cp16(uHl + d + 16, gl + 8);
                cp_commit();
            };

            issueH(0);
            for (int kt = 0; kt < HH / RKT; kt++) {
                cp_wait<0>();        // tile kt arrived
                __syncthreads();     // visible; everyone done with tile kt-1's buffer
                if (kt + 1 < HH / RKT) issueH(kt + 1);

                int b = kt & 1;
                const __nv_bfloat16* cHh = sHh + b * 64 * SHP;
                const __nv_bfloat16* cHl = sHl + b * 64 * SHP;
#pragma unroll
                for (int kc = 0; kc < RKT; kc += 16) {
                    int kw = kt * RKT + kc;
                    unsigned ah[4], al[4], bh[4][2], bl[4][2];
                    int r = row0;
                    ah[0] = *(unsigned*)&cHh[r * SHP + kc + 2 * tg];
                    ah[1] = *(unsigned*)&cHh[(r + 8) * SHP + kc + 2 * tg];
                    ah[2] = *(unsigned*)&cHh[r * SHP + kc + 2 * tg + 8];
                    ah[3] = *(unsigned*)&cHh[(r + 8) * SHP + kc + 2 * tg + 8];
                    al[0] = *(unsigned*)&cHl[r * SHP + kc + 2 * tg];
                    al[1] = *(unsigned*)&cHl[(r + 8) * SHP + kc + 2 * tg];
                    al[2] = *(unsigned*)&cHl[r * SHP + kc + 2 * tg + 8];
                    al[3] = *(unsigned*)&cHl[(r + 8) * SHP + kc + 2 * tg + 8];
#pragma unroll
                    for (int g = 0; g < 4; g++) {
                        int n = g * 16 + wn * 8 + gq;        // gate-aligned B row
                        bh[g][0] = *(unsigned*)&sWh[n][kw + 2 * tg];
                        bh[g][1] = *(unsigned*)&sWh[n][kw + 2 * tg + 8];
                        bl[g][0] = *(unsigned*)&sWl[n][kw + 2 * tg];
                        bl[g][1] = *(unsigned*)&sWl[n][kw + 2 * tg + 8];
                    }
#pragma unroll
                    for (int g = 0; g < 4; g++) {
                        mma16816(acc[g], ah, bh[g]);
                        mma16816(acc[g], ah, bl[g]);
                        mma16816(acc[g], al, bh[g]);
                    }
                }
            }
        }

        // ---- in-register epilogue: thread owns (row0+rr*8, jloc+cc), all 4 gates ----
#pragma unroll
        for (int rr = 0; rr < 2; rr++) {
            __nv_bfloat16 hh[2], hl[2];
#pragma unroll
            for (int cc = 0; cc < 2; cc++) {
                int fi = rr * 2 + cc;
                float pi = acc[0][fi] + xwf[0][rr][cc];
                float pf = acc[1][fi] + xwf[1][rr][cc];
                float pg = acc[2][fi] + xwf[2][rr][cc];
                float po = acc[3][fi] + xwf[3][rr][cc];
                float iv = fsigmoid(pi);
                float fv = fsigmoid(pf);
                float gv = felu(pg);
                float ov = fsigmoid(po);
                float cn = fv * cb[rr][cc] + iv * gv;
                float hv = ov * felu(cn);
                cb[rr][cc] = cn;
                split_bf16(hv, hh[cc], hl[cc]);
            }
            size_t cidx = (size_t)(m0 + row0 + rr * 8) * HH + n0 + jloc;
            float2 cv; cv.x = cb[rr][0]; cv.y = cb[rr][1];
            *(float2*)(g_c + cidx) = cv;
            size_t hidx = ((size_t)s * BB + m0 + row0 + rr * 8) * HH + n0 + jloc;
            *(unsigned*)(g_h_hi + hidx) = *(unsigned*)hh;
            *(unsigned*)(g_h_lo + hidx) = *(unsigned*)hl;
        }

        gbar_g((unsigned)(s + 1), bbat);   // h_s visible to this batch group
    }
}

// ---------------- final FC: out[b] = h[S-1,b,:] . fc_w + fc_b ----------------
__global__ void k_fc(const float* __restrict__ fcw, const float* __restrict__ fcb,
                     float* __restrict__ out) {
    __shared__ float red[4];
    int b = blockIdx.x, tid = threadIdx.x;
    size_t base = ((size_t)(SS - 1) * BB + b) * HH;
    float sum = 0.f;
    for (int j = tid; j < HH; j += 128)
        sum += (__bfloat162float(g_h_hi[base + j]) + __bfloat162float(g_h_lo[base + j])) * fcw[j];
#pragma unroll
    for (int o = 16; o; o >>= 1) sum += __shfl_xor_sync(0xFFFFFFFFu, sum, o);
    if ((tid & 31) == 0) red[tid >> 5] = sum;
    __syncthreads();
    if (tid == 0) out[b] = red[0] + red[1] + red[2] + red[3] + fcb[0];
}

// ---------------- launch ----------------
extern "C" void kernel_launch(void* const* d_in, const int* in_sizes, int n_in,
                              void* d_out, int out_size) {
    const float* x    = (const float*)d_in[0];
    const float* wih1 = (const float*)d_in[1];
    const float* whh1 = (const float*)d_in[2];
    const float* b1   = (const float*)d_in[3];
    const float* wih2 = (const float*)d_in[4];
    const float* whh2 = (const float*)d_in[5];
    const float* b2   = (const float*)d_in[6];
    const float* wih3 = (const float*)d_in[7];
    const float* whh3 = (const float*)d_in[8];
    const float* b3   = (const float*)d_in[9];
    const float* fcw  = (const float*)d_in[10];
    const float* fcb  = (const float*)d_in[11];

    cudaFuncSetAttribute(k_rec, cudaFuncAttributeMaxDynamicSharedMemorySize, SMEM_REC);
    cudaFuncSetAttribute(k_gemm_xw, cudaFuncAttributeMaxDynamicSharedMemorySize, XW_SMEM);

    k_split_w<<<(G4 * II + 255) / 256, 256>>>(wih1, 0, G4 * II);
    k_split_w<<<(G4 * HH + 255) / 256, 256>>>(whh1, 1, G4 * HH);
    k_split_w<<<(G4 * HH + 255) / 256, 256>>>(wih2, 2, G4 * HH);
    k_split_w<<<(G4 * HH + 255) / 256, 256>>>(whh2, 3, G4 * HH);
    k_split_w<<<(G4 * HH + 255) / 256, 256>>>(wih3, 4, G4 * HH);
    k_split_w<<<(G4 * HH + 255) / 256, 256>>>(whh3, 5, G4 * HH);
    k_split_x<<<(SS * BB * II + 255) / 256, 256>>>(x);

    const float* biases[3] = {b1, b2, b3};
    for (int L = 0; L < 3; L++) {
        dim3 gg(G4 / XBN, (SS * BB) / XBM);
        k_gemm_xw<<<gg, 256, XW_SMEM>>>(L, biases[L]);
        k_bar_init<<<1, 128>>>();
        k_rec<<<NCTA, 256, SMEM_REC>>>(L);
    }
    k_fc<<<BB, 128>>>(fcw, fcb, (float*)d_out);
}